// round 1
// baseline (speedup 1.0000x reference)
#include <cuda_runtime.h>
#include <math.h>

#define TRIALS 2048
#define CHUNK  8
#define NTHREADS 256
#define NV (TRIALS * 2)

__global__ __launch_bounds__(NTHREADS) void qv_kernel(
    const float* __restrict__ inp,
    const float* __restrict__ p_asr, const float* __restrict__ p_asu,
    const float* __restrict__ p_adr, const float* __restrict__ p_adu,
    const float* __restrict__ p_ksr, const float* __restrict__ p_ksu,
    const float* __restrict__ p_kdr, const float* __restrict__ p_kdu,
    float* __restrict__ out_v, float* __restrict__ out_diff, float* __restrict__ out_delta)
{
    __shared__ float4 s_in[TRIALS * 3 / 4];          // 1536 float4 = 24 KB
    __shared__ float s_wm[2][8], s_wc[2][8];

    const int tid = threadIdx.x;
    const int sess = blockIdx.x;

    // ---- coalesced stage of this session's input into smem ----
    const float4* g4 = (const float4*)(inp + (size_t)sess * (TRIALS * 3));
    #pragma unroll
    for (int i = 0; i < 6; ++i)
        s_in[tid + i * NTHREADS] = g4[tid + i * NTHREADS];

    // ---- params (L2-cached scalar loads) ----
    const float asr = 1.f / (1.f + expf(-p_asr[0]));
    const float asu = 1.f / (1.f + expf(-p_asu[0]));
    const float adr = 1.f / (1.f + expf(-p_adr[0]));
    const float adu = 1.f / (1.f + expf(-p_adu[0]));
    const float ksr = p_ksr[0], ksu = p_ksu[0], kdr = p_kdr[0], kdu = p_kdu[0];
    const float bsr = asr * ksr, bsu = asu * ksu, bdr = adr * kdr, bdu = adu * kdu;

    __syncthreads();

    // ---- pull my contiguous 8-trial chunk (24 floats) into registers ----
    float x[CHUNK * 3];
    float4* xr = (float4*)x;
    #pragma unroll
    for (int j = 0; j < 6; ++j)
        xr[j] = s_in[tid * 6 + j];

    // ---- phase 1: compose affine maps v' = m*v + c over my chunk ----
    float mL = 1.f, cL = 0.f, mR = 1.f, cR = 0.f;
    #pragma unroll
    for (int t = 0; t < CHUNK; ++t) {
        float cl = x[t * 3 + 0], crr = x[t * 3 + 1], o = x[t * 3 + 2];
        float no = 1.f - o;
        float w1 = cl * o, w2 = cl * no, w3 = crr * o, w4 = crr * no;
        float aL = w1 * asr + w2 * asu + w3 * adr + w4 * adu;
        float bL = w1 * bsr + w2 * bsu + w3 * bdr + w4 * bdu;
        float aR = w3 * asr + w4 * asu + w1 * adr + w2 * adu;
        float bR = w3 * bsr + w4 * bsu + w1 * bdr + w2 * bdu;
        float gL = 1.f - aL, gR = 1.f - aR;
        cL = gL * cL + bL;  mL = gL * mL;
        cR = gR * cR + bR;  mR = gR * mR;
    }

    // ---- warp-level inclusive scan (affine compose, earlier lane applied first) ----
    const int lane = tid & 31, warp = tid >> 5;
    #pragma unroll
    for (int d = 1; d < 32; d <<= 1) {
        float pmL = __shfl_up_sync(0xffffffffu, mL, d);
        float pcL = __shfl_up_sync(0xffffffffu, cL, d);
        float pmR = __shfl_up_sync(0xffffffffu, mR, d);
        float pcR = __shfl_up_sync(0xffffffffu, cR, d);
        if (lane >= d) {
            cL = mL * pcL + cL;  mL = mL * pmL;
            cR = mR * pcR + cR;  mR = mR * pmR;
        }
    }
    if (lane == 31) {
        s_wm[0][warp] = mL; s_wc[0][warp] = cL;
        s_wm[1][warp] = mR; s_wc[1][warp] = cR;
    }
    // exclusive within warp
    float emL = __shfl_up_sync(0xffffffffu, mL, 1);
    float ecL = __shfl_up_sync(0xffffffffu, cL, 1);
    float emR = __shfl_up_sync(0xffffffffu, mR, 1);
    float ecR = __shfl_up_sync(0xffffffffu, cR, 1);
    if (lane == 0) { emL = 1.f; ecL = 0.f; emR = 1.f; ecR = 0.f; }

    __syncthreads();
    if (tid == 0) {
        float m = 1.f, c = 0.f, m2 = 1.f, c2 = 0.f;
        #pragma unroll
        for (int w = 0; w < 8; ++w) {
            float tm = s_wm[0][w], tc = s_wc[0][w];
            s_wm[0][w] = m;  s_wc[0][w] = c;        // store exclusive warp prefix
            c = tm * c + tc;  m = tm * m;
            tm = s_wm[1][w]; tc = s_wc[1][w];
            s_wm[1][w] = m2; s_wc[1][w] = c2;
            c2 = tm * c2 + tc;  m2 = tm * m2;
        }
    }
    __syncthreads();

    // v before my chunk: apply (warp-exclusive then lane-exclusive) to v0 = 0
    float vL = emL * s_wc[0][warp] + ecL;
    float vR = emR * s_wc[1][warp] + ecR;

    // ---- phase 2: rescan my chunk with true starting v, write outputs ----
    const size_t ob = (size_t)sess * NV + (size_t)tid * (CHUNK * 2);
    float4* pv = (float4*)(out_v + ob);
    float4* pd = (float4*)(out_diff + ob);
    float4* pe = (float4*)(out_delta + ob);

    #pragma unroll
    for (int u = 0; u < CHUNK / 2; ++u) {
        float fv[4], fd[4], fe[4];
        #pragma unroll
        for (int h = 0; h < 2; ++h) {
            int t = 2 * u + h;
            float cl = x[t * 3 + 0], crr = x[t * 3 + 1], o = x[t * 3 + 2];
            float no = 1.f - o;
            float w1 = cl * o, w2 = cl * no, w3 = crr * o, w4 = crr * no;
            float aL = w1 * asr + w2 * asu + w3 * adr + w4 * adu;
            float bL = w1 * bsr + w2 * bsu + w3 * bdr + w4 * bdu;
            float aR = w3 * asr + w4 * asu + w1 * adr + w2 * adu;
            float bR = w3 * bsr + w4 * bsu + w1 * bdr + w2 * bdu;
            float D  = w1 + w2 + w3 + w4;
            float CLs = w1 * ksr + w2 * ksu + w3 * kdr + w4 * kdu;
            float CRs = w3 * ksr + w4 * ksu + w1 * kdr + w2 * kdu;
            float dL = bL - aL * vL;
            float dR = bR - aR * vR;
            fd[2 * h + 0] = CLs - D * vL;
            fd[2 * h + 1] = CRs - D * vR;
            fe[2 * h + 0] = dL;
            fe[2 * h + 1] = dR;
            vL += dL;
            vR += dR;
            fv[2 * h + 0] = vL;
            fv[2 * h + 1] = vR;
        }
        pv[u] = make_float4(fv[0], fv[1], fv[2], fv[3]);
        pd[u] = make_float4(fd[0], fd[1], fd[2], fd[3]);
        pe[u] = make_float4(fe[0], fe[1], fe[2], fe[3]);
    }
}

extern "C" void kernel_launch(void* const* d_in, const int* in_sizes, int n_in,
                              void* d_out, int out_size)
{
    const float* inp = (const float*)d_in[0];
    float* out = (float*)d_out;
    const int n_sess = in_sizes[0] / (TRIALS * 3);
    const size_t per = (size_t)n_sess * TRIALS * 2;

    qv_kernel<<<n_sess, NTHREADS>>>(
        inp,
        (const float*)d_in[1], (const float*)d_in[2],
        (const float*)d_in[3], (const float*)d_in[4],
        (const float*)d_in[5], (const float*)d_in[6],
        (const float*)d_in[7], (const float*)d_in[8],
        out, out + per, out + 2 * per);
}

// round 2
// speedup vs baseline: 1.0641x; 1.0641x over previous
#include <cuda_runtime.h>
#include <math.h>

#define TRIALS 2048
#define CHUNK  8
#define NTHREADS 256
#define NV (TRIALS * 2)

// select among 4 register-resident values by 2-bit index (compiles to SELs)
__device__ __forceinline__ float sel4(float t0, float t1, float t2, float t3, unsigned idx) {
    float a = (idx & 1u) ? t1 : t0;
    float b = (idx & 1u) ? t3 : t2;
    return (idx & 2u) ? b : a;
}

__global__ __launch_bounds__(NTHREADS, 6) void qv_kernel(
    const float* __restrict__ inp,
    const float* __restrict__ p_asr, const float* __restrict__ p_asu,
    const float* __restrict__ p_adr, const float* __restrict__ p_adu,
    const float* __restrict__ p_ksr, const float* __restrict__ p_ksu,
    const float* __restrict__ p_kdr, const float* __restrict__ p_kdu,
    float* __restrict__ out_v, float* __restrict__ out_diff, float* __restrict__ out_delta)
{
    __shared__ float4 s_in[TRIALS * 3 / 4];          // 1536 float4 = 24 KB
    __shared__ float s_wm[2][8], s_wc[2][8];

    const int tid = threadIdx.x;
    const int sess = blockIdx.x;

    // ---- coalesced stage of this session's input into smem ----
    const float4* g4 = (const float4*)(inp + (size_t)sess * (TRIALS * 3));
    #pragma unroll
    for (int i = 0; i < 6; ++i)
        s_in[tid + i * NTHREADS] = g4[tid + i * NTHREADS];

    // ---- params: 4-entry tables indexed by (cl<<1)|o ----
    // idx: 0 = diff,unrew  1 = diff,rew  2 = same,unrew  3 = same,rew   (for LEFT side)
    // RIGHT side uses idx ^ 2.
    const float Asr = 1.f / (1.f + expf(-p_asr[0]));
    const float Asu = 1.f / (1.f + expf(-p_asu[0]));
    const float Adr = 1.f / (1.f + expf(-p_adr[0]));
    const float Adu = 1.f / (1.f + expf(-p_adu[0]));
    const float Ksr = p_ksr[0], Ksu = p_ksu[0], Kdr = p_kdr[0], Kdu = p_kdu[0];

    __syncthreads();

    // ---- read my contiguous 8-trial chunk, compress to 2 bits/trial ----
    unsigned code = 0;
    {
        #pragma unroll
        for (int j = 0; j < 6; ++j) {
            float4 q = s_in[tid * 6 + j];
            // each float4 holds 4 floats of the (trial,3) stream; handle via flat view
            float f[4] = {q.x, q.y, q.z, q.w};
            #pragma unroll
            for (int e = 0; e < 4; ++e) {
                int flat = j * 4 + e;          // 0..23
                int t = flat / 3, c = flat - 3 * t;
                unsigned bit = (f[e] > 0.5f) ? 1u : 0u;
                if (c == 0) code |= bit << (2 * t + 1);        // chose_left
                else if (c == 2) code |= bit << (2 * t);       // outcome
                // c == 1 (chose_right) is redundant: cr = 1 - cl
            }
        }
    }

    // ---- phase 1: compose affine maps v' = m*v + c over my chunk ----
    float mL = 1.f, cL = 0.f, mR = 1.f, cR = 0.f;
    #pragma unroll
    for (int t = 0; t < CHUNK; ++t) {
        unsigned idx = (code >> (2 * t)) & 3u;
        unsigned jdx = idx ^ 2u;
        float aL = sel4(Adu, Adr, Asu, Asr, idx);
        float kL = sel4(Kdu, Kdr, Ksu, Ksr, idx);
        float aR = sel4(Adu, Adr, Asu, Asr, jdx);
        float kR = sel4(Kdu, Kdr, Ksu, Ksr, jdx);
        cL = fmaf(aL, kL - cL, cL);  mL = fmaf(-aL, mL, mL);
        cR = fmaf(aR, kR - cR, cR);  mR = fmaf(-aR, mR, mR);
    }

    // ---- warp-level inclusive scan (affine compose, earlier lane first) ----
    const int lane = tid & 31, warp = tid >> 5;
    #pragma unroll
    for (int d = 1; d < 32; d <<= 1) {
        float pmL = __shfl_up_sync(0xffffffffu, mL, d);
        float pcL = __shfl_up_sync(0xffffffffu, cL, d);
        float pmR = __shfl_up_sync(0xffffffffu, mR, d);
        float pcR = __shfl_up_sync(0xffffffffu, cR, d);
        if (lane >= d) {
            cL = mL * pcL + cL;  mL = mL * pmL;
            cR = mR * pcR + cR;  mR = mR * pmR;
        }
    }
    if (lane == 31) {
        s_wm[0][warp] = mL; s_wc[0][warp] = cL;
        s_wm[1][warp] = mR; s_wc[1][warp] = cR;
    }
    // exclusive within warp
    float emL = __shfl_up_sync(0xffffffffu, mL, 1);
    float ecL = __shfl_up_sync(0xffffffffu, cL, 1);
    float emR = __shfl_up_sync(0xffffffffu, mR, 1);
    float ecR = __shfl_up_sync(0xffffffffu, cR, 1);
    if (lane == 0) { emL = 1.f; ecL = 0.f; emR = 1.f; ecR = 0.f; }

    __syncthreads();
    if (tid == 0) {
        float m = 1.f, c = 0.f, m2 = 1.f, c2 = 0.f;
        #pragma unroll
        for (int w = 0; w < 8; ++w) {
            float tm = s_wm[0][w], tc = s_wc[0][w];
            s_wm[0][w] = m;  s_wc[0][w] = c;        // exclusive warp prefix
            c = tm * c + tc;  m = tm * m;
            tm = s_wm[1][w]; tc = s_wc[1][w];
            s_wm[1][w] = m2; s_wc[1][w] = c2;
            c2 = tm * c2 + tc;  m2 = tm * m2;
        }
    }
    __syncthreads();

    // v before my chunk: apply warp-exclusive then lane-exclusive prefix to v0 = 0
    float vL = emL * s_wc[0][warp] + ecL;
    float vR = emR * s_wc[1][warp] + ecR;

    // ---- phase 2: rescan my chunk from the 2-bit codes, write outputs ----
    const size_t ob = (size_t)sess * NV + (size_t)tid * (CHUNK * 2);
    float4* pv = (float4*)(out_v + ob);
    float4* pd = (float4*)(out_diff + ob);
    float4* pe = (float4*)(out_delta + ob);

    #pragma unroll
    for (int u = 0; u < CHUNK / 2; ++u) {
        float fv[4], fd[4], fe[4];
        #pragma unroll
        for (int h = 0; h < 2; ++h) {
            int t = 2 * u + h;
            unsigned idx = (code >> (2 * t)) & 3u;
            unsigned jdx = idx ^ 2u;
            float aL = sel4(Adu, Adr, Asu, Asr, idx);
            float kL = sel4(Kdu, Kdr, Ksu, Ksr, idx);
            float aR = sel4(Adu, Adr, Asu, Asr, jdx);
            float kR = sel4(Kdu, Kdr, Ksu, Ksr, jdx);
            float difL = kL - vL, difR = kR - vR;
            float dL = aL * difL, dR = aR * difR;
            fd[2 * h + 0] = difL;  fd[2 * h + 1] = difR;
            fe[2 * h + 0] = dL;    fe[2 * h + 1] = dR;
            vL += dL;  vR += dR;
            fv[2 * h + 0] = vL;    fv[2 * h + 1] = vR;
        }
        __stcs(pv + u, make_float4(fv[0], fv[1], fv[2], fv[3]));
        __stcs(pd + u, make_float4(fd[0], fd[1], fd[2], fd[3]));
        __stcs(pe + u, make_float4(fe[0], fe[1], fe[2], fe[3]));
    }
}

extern "C" void kernel_launch(void* const* d_in, const int* in_sizes, int n_in,
                              void* d_out, int out_size)
{
    const float* inp = (const float*)d_in[0];
    float* out = (float*)d_out;
    const int n_sess = in_sizes[0] / (TRIALS * 3);
    const size_t per = (size_t)n_sess * TRIALS * 2;

    qv_kernel<<<n_sess, NTHREADS>>>(
        inp,
        (const float*)d_in[1], (const float*)d_in[2],
        (const float*)d_in[3], (const float*)d_in[4],
        (const float*)d_in[5], (const float*)d_in[6],
        (const float*)d_in[7], (const float*)d_in[8],
        out, out + per, out + 2 * per);
}